// round 16
// baseline (speedup 1.0000x reference)
#include <cuda_runtime.h>
#include <cuda_fp16.h>
#include <cstdint>

// R15: fp16 mma LSTM, 8 warps x (32x32) warp tiles (was 16 x (16x32)).
// LDSM bytes per MMA cut 1.5x (2A+2B LDSM per 8 MMAs): smem port was the
// measured bottleneck (L1=52.5%, ~32K cyc/step of LDSM vs 16K tensor).
// 128 persistent CTAs x 64 rows; A-image ping-pong; one sync per slab.

#define HOR 64
#define FDIM 64
#define ORD 16
#define KH 256
#define KTOT 336
#define MROWS 64
#define NCTAS 128
#define NTHREADS 256
#define NTILES 8
#define NSLB 3                 /* slabs per tile */
#define SLABK 112              /* K rows per slab */
#define BSTRK 120              /* B col stride (fp16): 112 data + 8 pad */
#define ASTR2 344              /* A row stride (fp16): 336 data + 8 pad */
#define SLABB (128*BSTRK*2)    /* 30720 B */
#define ABUF  (64*ASTR2*2)     /* 44032 B */

// smem byte offsets
#define SA 0                   /* A: 2 x 44032 = 88064 */
#define SB 88064               /* B: 2 x 30720 = 61440 */
#define SC 149504              /* c: 256*65*4  = 66560 */
#define SBIAS 216064           /* 1024*4 */
#define SDW 220160             /* 256*4  */
#define SDOT 221184            /* 4*64*4 = 1024 */
#define SMEM_TOTAL 222208

__device__ __align__(16) __half W_img[(size_t)NTILES*NSLB*128*BSTRK]; // 737 KB
__device__ float bias_img[NTILES*128];

static __device__ __forceinline__ float sig_(float x){ return 1.0f/(1.0f+__expf(-x)); }
static __device__ __forceinline__ float th_(float x){ return 1.0f - 2.0f/(__expf(2.0f*x)+1.0f); }
static __device__ __forceinline__ unsigned smem_u32(const void* p){
    unsigned a; asm("{ .reg .u64 t; cvta.to.shared.u64 t, %1; cvt.u32.u64 %0, t; }"
                    : "=r"(a) : "l"(p)); return a;
}
static __device__ __forceinline__ void mma16(float* d, unsigned a0,unsigned a1,unsigned a2,unsigned a3,
                                             unsigned b0,unsigned b1){
    asm volatile("mma.sync.aligned.m16n8k16.row.col.f32.f16.f16.f32 "
        "{%0,%1,%2,%3}, {%4,%5,%6,%7}, {%8,%9}, {%0,%1,%2,%3};"
        : "+f"(d[0]),"+f"(d[1]),"+f"(d[2]),"+f"(d[3])
        : "r"(a0),"r"(a1),"r"(a2),"r"(a3),"r"(b0),"r"(b1));
}
static __device__ __forceinline__ void ldsm4(unsigned& r0,unsigned& r1,unsigned& r2,unsigned& r3,
                                             unsigned a){
    asm volatile("ldmatrix.sync.aligned.m8n8.x4.shared.b16 {%0,%1,%2,%3}, [%4];"
        : "=r"(r0),"=r"(r1),"=r"(r2),"=r"(r3) : "r"(a));
}

// W_img[n][s][c][k120]: col c: jj=c>>3, p=c&7; unit=4*(jj>>1)+(p>>1),
// gate=2*(jj&1)+(p&1); src col = gate*256 + n*32 + unit.  (unchanged vs R14)
__global__ void prep(const float* __restrict__ Wk, const float* __restrict__ Wr,
                     const float* __restrict__ bias){
    int b = blockIdx.x;                 // 0..23
    int n = b / NSLB, s = b % NSLB;
    int c = threadIdx.x;                // 0..127
    int jj = c >> 3, p = c & 7;
    int u = 4*(jj>>1) + (p>>1);
    int g = 2*(jj&1) + (p&1);
    int col = g*256 + n*32 + u;
    __half* dst = W_img + ((size_t)(n*NSLB + s)*128 + c)*BSTRK;
    for (int kk = 0; kk < BSTRK; kk++) {
        float w = 0.f;
        int k = s*SLABK + kk;
        if (kk < SLABK && k < KTOT)
            w = (k < 80) ? Wk[(size_t)k*1024 + col] : Wr[(size_t)(k-80)*1024 + col];
        dst[kk] = __float2half_rn(w);
    }
    if (s == 0) bias_img[n*128 + c] = bias[col];
}

extern __shared__ char smc[];

static __device__ __forceinline__ void cpslab(unsigned dst, const char* src, int tid){
    for (int i = tid; i < SLABB/16; i += NTHREADS)
        asm volatile("cp.async.cg.shared.global [%0], [%1], 16;"
            :: "r"(dst + i*16), "l"(src + (size_t)i*16) : "memory");
    asm volatile("cp.async.commit_group;" ::: "memory");
}

__global__ void __launch_bounds__(NTHREADS,1)
lstm_mma(const float* __restrict__ x, const float* __restrict__ y0,
         const float* __restrict__ dw, const float* __restrict__ db,
         float* __restrict__ out)
{
    const int tid = threadIdx.x, lane = tid & 31, wid = tid >> 5;
    const int mw = wid >> 2, nw = wid & 3;       // 2 M-warps (32 rows) x 4 N-warps (32 cols)
    const int R0 = mw * 32;
    const int qr = lane >> 2, qq = lane & 3;
    const int cta = blockIdx.x, row0 = cta * MROWS;

    float* cs     = (float*)(smc + SC);
    float* bias_s = (float*)(smc + SBIAS);
    float* dw_s   = (float*)(smc + SDW);
    float* dotb   = (float*)(smc + SDOT);
    const unsigned sbA = smem_u32(smc + SA);
    const unsigned sbB = smem_u32(smc + SB);

    // ldmatrix lane offsets (bytes). Two A frags (rows R0.., R0+16..), two B frag pairs.
    const unsigned offA0 = ((unsigned)(R0 + (lane & 15)) * ASTR2 + (lane >> 4) * 8u) * 2u;
    const unsigned offA1 = offA0 + 16u * ASTR2 * 2u;
    const unsigned offB0 = (((unsigned)nw*32u + (lane >> 4)*8u + (lane & 7u)) * BSTRK
                            + ((lane >> 3) & 1u) * 8u) * 2u;
    const unsigned offB1 = offB0 + 16u * BSTRK * 2u;

    for (int i = tid; i < 256*65; i += NTHREADS) cs[i] = 0.f;
    for (int i = tid; i < NTILES*128; i += NTHREADS) bias_s[i] = bias_img[i];
    if (tid < KH) dw_s[tid] = __ldg(dw + tid);
    const float db0 = __ldg(db);
    {   // zero h region of A buf0 (t=0 reads it)
        __half2 z2 = __floats2half2_rn(0.f, 0.f);
        __half* A0 = (__half*)(smc + SA);
        for (int i = tid; i < 64*128; i += NTHREADS) {
            int r = i >> 7, u2 = i & 127;
            *(__half2*)(A0 + r*ASTR2 + 80 + 2*u2) = z2;
        }
    }
    float ypr[ORD];
    if (tid < MROWS) {
#pragma unroll
        for (int j = 0; j < ORD; j++) ypr[j] = __ldg(y0 + (size_t)(row0+tid)*ORD + j);
    }
    __syncthreads();

    for (int t = 0; t < HOR; t++) {
        __half* Ac = (__half*)(smc + SA + (t & 1)*ABUF);        // GEMM reads
        __half* An = (__half*)(smc + SA + ((t+1) & 1)*ABUF);    // epilogue h dest
        const unsigned sbAc = sbA + (unsigned)(t & 1)*ABUF;

        // ---- stage x_t (fp16 pairs) + yp into Ac ----
#pragma unroll
        for (int i = 0; i < 8; i++) {
            int e = i*NTHREADS + tid;            // 0..2047 pairs
            int r = e >> 5, kp = e & 31;
            float2 xv = *(const float2*)(x + ((size_t)(row0+r)*HOR + t)*FDIM + kp*2);
            *(__half2*)(Ac + r*ASTR2 + kp*2) = __floats2half2_rn(xv.x, xv.y);
        }
        if (tid < MROWS) {
#pragma unroll
            for (int j = 0; j < ORD/2; j++)
                *(__half2*)(Ac + tid*ASTR2 + 64 + 2*j) = __floats2half2_rn(ypr[2*j], ypr[2*j+1]);
        }
        cpslab(sbB, (const char*)W_img, tid);    // copy q=0 -> buf0
        __syncthreads();                          // staging + h(from t-1 epilogue) visible

        float dot0 = 0.f, dot1 = 0.f, dot2 = 0.f, dot3 = 0.f;

        for (int n = 0; n < NTILES; n++) {
            float acc[4][2][4];                   // [j-subtile][m-frag][quad]
#pragma unroll
            for (int j = 0; j < 4; j++)
#pragma unroll
                for (int m = 0; m < 2; m++)
#pragma unroll
                    for (int q = 0; q < 4; q++) acc[j][m][q] = 0.f;

            for (int s = 0; s < NSLB; s++) {
                const int q = n*NSLB + s;
                asm volatile("cp.async.wait_group 0;" ::: "memory");   // copy q done
                __syncthreads();   // copy q visible to all; MMA q-1 finished
                if (q + 1 < NTILES*NSLB)
                    cpslab(sbB + (unsigned)((q+1)&1)*SLABB,
                           (const char*)W_img + (size_t)(q+1)*SLABB, tid);

                const unsigned bufB = sbB + (unsigned)(q & 1)*SLABB;
                const unsigned akb  = sbAc + (unsigned)(s*SLABK)*2u;
#pragma unroll
                for (int kk = 0; kk < SLABK/16; kk++) {               // 7 chunks
                    unsigned a00,a01,a02,a03, a10,a11,a12,a13;
                    unsigned b00,b01,b10,b11, b20,b21,b30,b31;
                    ldsm4(a00,a01,a02,a03, akb + offA0 + kk*32);
                    ldsm4(a10,a11,a12,a13, akb + offA1 + kk*32);
                    ldsm4(b00,b01,b10,b11, bufB + offB0 + kk*32);
                    ldsm4(b20,b21,b30,b31, bufB + offB1 + kk*32);
                    mma16(acc[0][0], a00,a01,a02,a03, b00,b01);
                    mma16(acc[0][1], a10,a11,a12,a13, b00,b01);
                    mma16(acc[1][0], a00,a01,a02,a03, b10,b11);
                    mma16(acc[1][1], a10,a11,a12,a13, b10,b11);
                    mma16(acc[2][0], a00,a01,a02,a03, b20,b21);
                    mma16(acc[2][1], a10,a11,a12,a13, b20,b21);
                    mma16(acc[3][0], a00,a01,a02,a03, b30,b31);
                    mma16(acc[3][1], a10,a11,a12,a13, b30,b31);
                }
            }

            // ---- epilogue tile n: gates, c update, h -> An (fp16), dense dot ----
#pragma unroll
            for (int jh = 0; jh < 2; jh++) {
                const int U  = n*32 + 4*(nw*2 + jh) + qq;
                const int bb = n*128 + (nw*4 + jh*2)*8 + 2*qq;
                const float bi = bias_s[bb],   bf = bias_s[bb+1];
                const float bg = bias_s[bb+8], bo = bias_s[bb+9];
                const float dwu = dw_s[U];
                float* cU = cs + U*65;
#pragma unroll
                for (int m = 0; m < 2; m++) {
                    const int rb = R0 + m*16;
                    {
                        const int r = rb + qr;
                        float zi = acc[2*jh][m][0]+bi, zf = acc[2*jh][m][1]+bf;
                        float zg = acc[2*jh+1][m][0]+bg, zo = acc[2*jh+1][m][1]+bo;
                        float cn = sig_(zf)*cU[r] + sig_(zi)*th_(zg);
                        cU[r] = cn;
                        float h = sig_(zo)*th_(cn);
                        An[r*ASTR2 + 80 + U] = __float2half_rn(h);
                        if (m == 0) dot0 += h*dwu; else dot2 += h*dwu;
                    }
                    {
                        const int r = rb + qr + 8;
                        float zi = acc[2*jh][m][2]+bi, zf = acc[2*jh][m][3]+bf;
                        float zg = acc[2*jh+1][m][2]+bg, zo = acc[2*jh+1][m][3]+bo;
                        float cn = sig_(zf)*cU[r] + sig_(zi)*th_(zg);
                        cU[r] = cn;
                        float h = sig_(zo)*th_(cn);
                        An[r*ASTR2 + 80 + U] = __float2half_rn(h);
                        if (m == 0) dot1 += h*dwu; else dot3 += h*dwu;
                    }
                }
            }
        }

        // ---- dense reduce: quad shfl (over qq), then across 4 N-warps ----
        dot0 += __shfl_xor_sync(0xffffffffu, dot0, 1);
        dot0 += __shfl_xor_sync(0xffffffffu, dot0, 2);
        dot1 += __shfl_xor_sync(0xffffffffu, dot1, 1);
        dot1 += __shfl_xor_sync(0xffffffffu, dot1, 2);
        dot2 += __shfl_xor_sync(0xffffffffu, dot2, 1);
        dot2 += __shfl_xor_sync(0xffffffffu, dot2, 2);
        dot3 += __shfl_xor_sync(0xffffffffu, dot3, 1);
        dot3 += __shfl_xor_sync(0xffffffffu, dot3, 2);
        if (qq == 0) {
            dotb[nw*MROWS + R0 + qr]      = dot0;
            dotb[nw*MROWS + R0 + qr + 8]  = dot1;
            dotb[nw*MROWS + R0 + qr + 16] = dot2;
            dotb[nw*MROWS + R0 + qr + 24] = dot3;
        }
        __syncthreads();
        if (tid < MROWS) {
            float p = dotb[tid] + dotb[MROWS+tid] + dotb[2*MROWS+tid] + dotb[3*MROWS+tid] + db0;
            out[(size_t)(row0+tid)*HOR + t] = p;
#pragma unroll
            for (int j = ORD-1; j > 0; j--) ypr[j] = ypr[j-1];
            ypr[0] = p;
        }
        __syncthreads();   // h/dot settled before next staging
    }
}

extern "C" void kernel_launch(void* const* d_in, const int* in_sizes, int n_in,
                              void* d_out, int out_size) {
    const float* x    = (const float*)d_in[0];
    const float* y0   = (const float*)d_in[1];
    const float* Wk   = (const float*)d_in[2];   // [80, 1024]
    const float* Wr   = (const float*)d_in[3];   // [256, 1024]
    const float* bias = (const float*)d_in[4];   // [1024]
    const float* dw   = (const float*)d_in[5];   // [256, 1]
    const float* db   = (const float*)d_in[6];   // [1]
    float* out = (float*)d_out;                  // [8192, 64, 1]
    cudaFuncSetAttribute(lstm_mma, cudaFuncAttributeMaxDynamicSharedMemorySize, SMEM_TOTAL);
    prep<<<NTILES*NSLB, 128>>>(Wk, Wr, bias);
    lstm_mma<<<NCTAS, NTHREADS, SMEM_TOTAL>>>(x, y0, dw, db, out);
}